// round 4
// baseline (speedup 1.0000x reference)
#include <cuda_runtime.h>
#include <cstdint>

#define D 128
#define C 64
#define EPSF 1e-5f

// Scratch (device globals — allocations are forbidden)
__device__ float g_protoSum[C * D];
__device__ float g_counts[C];

// ---------------------------------------------------------------------------
// packed f32x2 helpers (sm_100a FFMA2/FADD2 path)
// ---------------------------------------------------------------------------
__device__ __forceinline__ void add_f32x2(unsigned long long& d,
                                          unsigned long long a,
                                          unsigned long long b) {
    asm("add.rn.f32x2 %0, %1, %2;" : "=l"(d) : "l"(a), "l"(b));
}
__device__ __forceinline__ void fma_f32x2(unsigned long long& d,
                                          unsigned long long a,
                                          unsigned long long b) {
    asm("fma.rn.f32x2 %0, %1, %2, %0;" : "+l"(d) : "l"(a), "l"(b));
}

// ---------------------------------------------------------------------------
// Kernel 0: zero scratch + output
// ---------------------------------------------------------------------------
__global__ void k_zero(float* out) {
    int t = blockIdx.x * blockDim.x + threadIdx.x;
    if (t < C * D) g_protoSum[t] = 0.0f;
    if (t < C) g_counts[t] = 0.0f;
    if (t == 0) out[0] = 0.0f;
}

// ---------------------------------------------------------------------------
// Kernel 1: segment-sum with per-CTA smem staging.
// 64 CTAs x 256 threads; each CTA accumulates its row-chunk into smem
// (spread-bank ATOMS), then flushes 8192 global RED.ADD (4x fewer than R3).
// ---------------------------------------------------------------------------
__global__ __launch_bounds__(256) void k_accum(const float* __restrict__ x,
                                               const int* __restrict__ y,
                                               int m) {
    __shared__ float sProto[C * D];
    __shared__ float sCnt[C];
    int tid = threadIdx.x;
    for (int i = tid; i < C * D; i += 256) sProto[i] = 0.0f;
    if (tid < C) sCnt[tid] = 0.0f;
    __syncthreads();

    int rpc = (m + gridDim.x - 1) / gridDim.x;
    int r0  = blockIdx.x * rpc;
    int j   = tid & (D - 1);   // dim (warp-contiguous -> coalesced x, spread banks)
    int rh  = tid >> 7;        // 0/1: two rows in flight

    for (int r = rh; r < rpc; r += 2) {
        int row = r0 + r;
        if (row >= m) break;
        int c = y[row];                           // warp-uniform broadcast
        float v = x[(size_t)row * D + j];
        atomicAdd(&sProto[c * D + j], v);
        if (j == 0) atomicAdd(&sCnt[c], 1.0f);
    }
    __syncthreads();

    for (int i = tid; i < C * D; i += 256) atomicAdd(&g_protoSum[i], sProto[i]);
    if (tid < C) atomicAdd(&g_counts[tid], sCnt[tid]);
}

// ---------------------------------------------------------------------------
// Kernel 2: distances + log_softmax + NLL (fuses prototype finalize).
// 256 threads = 64 targets x 4 class-groups of 16. Prototypes staged in smem
// as q = EPS - proto so the inner loop is packed: t = x + q; acc += t * |t|.
// x read straight from global (L1-resident). ~35KB smem -> 4 CTAs/SM.
// ---------------------------------------------------------------------------
__global__ __launch_bounds__(256, 4) void k_loss(const float* __restrict__ x,
                                                 const int* __restrict__ y,
                                                 float* __restrict__ out,
                                                 int m) {
    __shared__ float q[C * D];        // EPS - prototype
    __shared__ float spmax[4 * 64];
    __shared__ float spsum[4 * 64];
    __shared__ float sdy[64];
    __shared__ float red[64];

    int tid = threadIdx.x;
    int i0  = blockIdx.x * 64;

    // ---- stage q = EPS - protoSum/cnt' (fused k_proto) ----
    for (int idx = tid; idx < C * D / 4; idx += 256) {
        float4 s = ((const float4*)g_protoSum)[idx];
        float cnt = g_counts[idx >> 5];           // 32 float4 per class row
        cnt += (cnt < 0.01f) ? 1.0f : 0.0f;
        float rc = __fdividef(1.0f, cnt);
        float4 qq;
        qq.x = EPSF - s.x * rc;
        qq.y = EPSF - s.y * rc;
        qq.z = EPSF - s.z * rc;
        qq.w = EPSF - s.w * rc;
        ((float4*)q)[idx] = qq;
    }
    __syncthreads();

    int tgt = tid & 63;
    int cg  = tid >> 6;               // warp-uniform -> q LDS broadcasts
    const ulonglong2* xrow = (const ulonglong2*)(x + (size_t)(m + i0 + tgt) * D);
    const float* qb = q + cg * 16 * D;

    unsigned long long acc[16];
#pragma unroll
    for (int k = 0; k < 16; k++) acc[k] = 0ull;

    const unsigned long long ABS2 = 0x7FFFFFFF7FFFFFFFull;

    for (int j4 = 0; j4 < D / 4; j4++) {
        ulonglong2 xv = xrow[j4];     // LDG.128: dims [4*j4 .. 4*j4+3] packed
#pragma unroll
        for (int cc = 0; cc < 16; cc++) {
            ulonglong2 qv = *(const ulonglong2*)(qb + cc * D + j4 * 4);
            unsigned long long t01, t23;
            add_f32x2(t01, xv.x, qv.x);           // t = x + (EPS - p)
            add_f32x2(t23, xv.y, qv.y);
            unsigned long long a01 = t01 & ABS2;  // |t| (2x LOP3, alu pipe)
            unsigned long long a23 = t23 & ABS2;
            fma_f32x2(acc[cc], t01, a01);         // acc += t * |t|
            fma_f32x2(acc[cc], t23, a23);
        }
    }

    // ---- unpack accumulators, partial softmax over this thread's 16 classes
    float dist[16];
    float pm = -1e30f;
#pragma unroll
    for (int cc = 0; cc < 16; cc++) {
        float lo = __uint_as_float((unsigned)(acc[cc] & 0xFFFFFFFFull));
        float hi = __uint_as_float((unsigned)(acc[cc] >> 32));
        float dv = (lo + hi) * (-1.0f / (float)D);
        dist[cc] = dv;
        pm = fmaxf(pm, dv);
    }
    spmax[cg * 64 + tgt] = pm;
    __syncthreads();

    float gmax = fmaxf(fmaxf(spmax[tgt], spmax[64 + tgt]),
                       fmaxf(spmax[128 + tgt], spmax[192 + tgt]));
    float se = 0.0f;
#pragma unroll
    for (int cc = 0; cc < 16; cc++) se += __expf(dist[cc] - gmax);
    spsum[cg * 64 + tgt] = se;

    int yc = y[m + i0 + tgt];
    if ((yc >> 4) == cg) sdy[tgt] = dist[yc & 15];
    __syncthreads();

    if (tid < 64) {
        float tot = spsum[tid] + spsum[64 + tid] + spsum[128 + tid] + spsum[192 + tid];
        red[tid] = -(sdy[tid] - gmax - __logf(tot));   // gmax valid: cg==0 thread
    }
    __syncthreads();

    if (tid == 0) {
        float s = 0.0f;
#pragma unroll 8
        for (int k = 0; k < 64; k++) s += red[k];
        atomicAdd(out, s / (float)m);
    }
}

// ---------------------------------------------------------------------------
// launch
// ---------------------------------------------------------------------------
extern "C" void kernel_launch(void* const* d_in, const int* in_sizes, int n_in,
                              void* d_out, int out_size) {
    const float* x = (const float*)d_in[0];
    const int*   y = (const int*)d_in[1];
    int n = in_sizes[1];
    int m = n / 2;
    float* out = (float*)d_out;

    k_zero<<<(C * D + 255) / 256, 256>>>(out);
    k_accum<<<64, 256>>>(x, y, m);
    k_loss<<<m / 64, 256>>>(x, y, out, m);
}

// round 5
// speedup vs baseline: 1.9436x; 1.9436x over previous
#include <cuda_runtime.h>
#include <cstdint>

#define D 128
#define C 64
#define EPSF 1e-5f

// q[c][j] = EPS - prototype[c][j]   (device scratch; allocations forbidden)
__device__ float g_q[C * D];

// ---------------------------------------------------------------------------
// Kernel 1: one CTA per class. Build list of matching support rows, then
// accumulate them with coalesced loads into registers. No global atomics,
// no zero-init pass, writes finalized q = EPS - sum/cnt'. CTA 0 zeroes out.
// ---------------------------------------------------------------------------
__global__ __launch_bounds__(256) void k_accum(const float* __restrict__ x,
                                               const int* __restrict__ y,
                                               float* __restrict__ out,
                                               int m) {
    __shared__ unsigned short list[4096];
    __shared__ int cnt;
    __shared__ float partial[D];

    int tid = threadIdx.x;
    int c   = blockIdx.x;
    if (tid == 0) cnt = 0;
    if (c == 0 && tid == 0) out[0] = 0.0f;
    __syncthreads();

    // phase 1: scan labels, collect matching row indices
    for (int i = tid; i < m; i += 256) {
        if (y[i] == c) {
            int p = atomicAdd(&cnt, 1);
            if (p < 4096) list[p] = (unsigned short)i;
        }
    }
    __syncthreads();
    int n = cnt < 4096 ? cnt : 4096;

    // phase 2: 2 row-streams x 128 dims; rows independent -> high MLP
    int j    = tid & (D - 1);
    int half = tid >> 7;
    float acc = 0.0f;
#pragma unroll 4
    for (int k = half; k < n; k += 2) {
        acc += x[(size_t)list[k] * D + j];
    }
    if (half == 1) partial[j] = acc;
    __syncthreads();
    if (half == 0) {
        float tot = acc + partial[j];
        float fc  = (n == 0) ? 1.0f : (float)n;   // counts + (counts<0.01)
        g_q[c * D + j] = EPSF - tot / fc;
    }
}

// ---------------------------------------------------------------------------
// Kernel 2: distances + log_softmax + NLL.
// 256 threads = 64 targets x 4 class-groups of 16 (cg warp-uniform ->
// q LDS broadcasts). x tile staged in smem (pad 132: conflict-free LDS.128).
// smem ~67.5KB -> 3 CTAs/SM; launch_bounds(256,3) gives ptxas ~85 regs.
// ---------------------------------------------------------------------------
#define XS_STRIDE 132

extern __shared__ float smem[];

__global__ __launch_bounds__(256, 3) void k_loss(const float* __restrict__ x,
                                                 const int* __restrict__ y,
                                                 float* __restrict__ out,
                                                 int m) {
    float* xs = smem;                 // 64 * 132
    float* qs = xs + 64 * XS_STRIDE;  // 64 * 128
    __shared__ float spmax[4 * 64];
    __shared__ float spsum[4 * 64];
    __shared__ float sdy[64];
    __shared__ float red[64];

    int tid = threadIdx.x;
    int i0  = blockIdx.x * 64;

    // stage x target tile (coalesced float4)
    const float4* xg = (const float4*)(x + (size_t)(m + i0) * D);
    for (int idx = tid; idx < 64 * (D / 4); idx += 256) {
        int r  = idx >> 5;
        int c4 = idx & 31;
        *(float4*)&xs[r * XS_STRIDE + c4 * 4] = xg[r * (D / 4) + c4];
    }
    // stage q tile
    for (int idx = tid; idx < C * D / 4; idx += 256) {
        ((float4*)qs)[idx] = ((const float4*)g_q)[idx];
    }
    __syncthreads();

    int tgt = tid & 63;
    int cg  = tid >> 6;
    const float4* xrow = (const float4*)&xs[tgt * XS_STRIDE];
    const float*  qb   = &qs[cg * 16 * D];

    float acc[16];
#pragma unroll
    for (int k = 0; k < 16; k++) acc[k] = 0.0f;

    for (int j4 = 0; j4 < D / 4; j4++) {
        float4 xv = xrow[j4];
#pragma unroll
        for (int cc = 0; cc < 16; cc++) {
            float4 qv = *(const float4*)&qb[cc * D + j4 * 4];
            float t0 = xv.x + qv.x;      // t = x + (EPS - p) = diff + EPS
            float t1 = xv.y + qv.y;
            float t2 = xv.z + qv.z;
            float t3 = xv.w + qv.w;
            float a = acc[cc];
            a = fmaf(t0, fabsf(t0), a);  // sign(t) * t^2
            a = fmaf(t1, fabsf(t1), a);
            a = fmaf(t2, fabsf(t2), a);
            a = fmaf(t3, fabsf(t3), a);
            acc[cc] = a;
        }
    }

    // partial softmax over this thread's 16 classes
    float dist[16];
    float pm = -1e30f;
#pragma unroll
    for (int cc = 0; cc < 16; cc++) {
        float dv = acc[cc] * (-1.0f / (float)D);
        dist[cc] = dv;
        pm = fmaxf(pm, dv);
    }
    spmax[cg * 64 + tgt] = pm;
    __syncthreads();

    float gmax = fmaxf(fmaxf(spmax[tgt], spmax[64 + tgt]),
                       fmaxf(spmax[128 + tgt], spmax[192 + tgt]));
    float se = 0.0f;
#pragma unroll
    for (int cc = 0; cc < 16; cc++) se += __expf(dist[cc] - gmax);
    spsum[cg * 64 + tgt] = se;

    int yc = y[m + i0 + tgt];
    if ((yc >> 4) == cg) sdy[tgt] = dist[yc & 15];
    __syncthreads();

    if (tid < 64) {
        float tot = spsum[tid] + spsum[64 + tid] + spsum[128 + tid] + spsum[192 + tid];
        red[tid] = -(sdy[tid] - gmax - __logf(tot));
    }
    __syncthreads();

    if (tid == 0) {
        float s = 0.0f;
#pragma unroll 8
        for (int k = 0; k < 64; k++) s += red[k];
        atomicAdd(out, s / (float)m);
    }
}

// ---------------------------------------------------------------------------
// launch
// ---------------------------------------------------------------------------
extern "C" void kernel_launch(void* const* d_in, const int* in_sizes, int n_in,
                              void* d_out, int out_size) {
    const float* x = (const float*)d_in[0];
    const int*   y = (const int*)d_in[1];
    int n = in_sizes[1];
    int m = n / 2;
    float* out = (float*)d_out;

    k_accum<<<C, 256>>>(x, y, out, m);

    size_t dynbytes = (size_t)(64 * XS_STRIDE + C * D) * sizeof(float);
    cudaFuncSetAttribute(k_loss, cudaFuncAttributeMaxDynamicSharedMemorySize,
                         (int)dynbytes);
    k_loss<<<m / 64, 256, dynbytes>>>(x, y, out, m);
}